// round 15
// baseline (speedup 1.0000x reference)
#include <cuda_runtime.h>
#include <math.h>

#define B_ 256
#define S_ 8
#define C_ 8
#define H_ 501
#define L_ 56
#define H2_ 1002
#define H3_ 1503
#define H4_ 2004

#define BM 64
#define BN 64
#define BK 16
#define PAD 4
#define LDS_ (BM + PAD)      // 68 floats, 272B rows -> 16B aligned
#define NTH 256

#define EDGE_NT 32           // ceil(2004/64)
#define EDGE_MT 4            // 256/64
#define NBE (EDGE_NT*EDGE_MT) // 128 edge blocks
#define GM_NT 8              // ceil(501/64)
#define GM_MT 8              // 512/64
#define NBG (GM_NT*GM_MT)    // 64 gatemap blocks

// ---------------- scratch ----------------
__device__ float d_hv  [B_*H_];
__device__ float d_nhs [B_*S_*H_];
__device__ float d_t1  [B_*H2_];
__device__ float d_gh  [B_*H3_];
__device__ float d_gi  [B_*S_*H3_];
__device__ float d_P   [B_*S_*H_];   // P cache per (b,s)
__device__ float d_Pt  [B_*H_];      // new P for row i
__device__ float d_SUM [B_*H_];
__device__ float d_hin [B_*H_];
__device__ float d_c0  [H_];
__device__ float d_part[EDGE_NT*B_];

__device__ __forceinline__ float sigmoidf_(float x){ return 1.f/(1.f+expf(-x)); }

__global__ void k_zero(float* p, int n){
    int i = blockIdx.x*blockDim.x + threadIdx.x;
    if (i < n) p[i] = 0.f;
}
__global__ void k_c0(const float* __restrict__ gb, const float* __restrict__ mb,
                     float* __restrict__ c0){
    int h = blockIdx.x*blockDim.x + threadIdx.x;
    if (h < H_) c0[h] = sigmoidf_(gb[h]) * mb[h];
}

// ---------------- generic double-buffered SGEMM: C = act(A @ W^T + bias) ----------------
__global__ __launch_bounds__(NTH)
void k_gemm(const float* __restrict__ A, int lda,
            const float* __restrict__ W,
            const float* __restrict__ bias,
            float* __restrict__ Cm, int ldc,
            int M, int N, int K, int relu)
{
    __shared__ float As[2][BK][LDS_];
    __shared__ float Ws[2][BK][LDS_];
    const int tid = threadIdx.x;
    const int m0 = blockIdx.y*BM, n0 = blockIdx.x*BN;
    const int lk = tid & 15, lr = tid >> 4;
    const int tx = tid & 15, ty = tid >> 4;
    float acc[4][4] = {};
    float ra[4], rb[4];
    const int nt = (K + BK - 1)/BK;

    #pragma unroll
    for (int u = 0; u < 4; u++){
        int gm = m0 + lr + 16*u;
        int gn = n0 + lr + 16*u;
        ra[u] = (lk < K && gm < M) ? A[gm*lda + lk] : 0.f;
        rb[u] = (lk < K && gn < N) ? W[gn*K  + lk] : 0.f;
    }
    #pragma unroll
    for (int u = 0; u < 4; u++){
        As[0][lk][lr+16*u] = ra[u];
        Ws[0][lk][lr+16*u] = rb[u];
    }
    __syncthreads();

    for (int t = 0; t < nt; t++){
        const int buf = t & 1;
        if (t+1 < nt){
            int gk = (t+1)*BK + lk;
            #pragma unroll
            for (int u = 0; u < 4; u++){
                int gm = m0 + lr + 16*u;
                int gn = n0 + lr + 16*u;
                ra[u] = (gk < K && gm < M) ? A[gm*lda + gk] : 0.f;
                rb[u] = (gk < K && gn < N) ? W[gn*K  + gk] : 0.f;
            }
        }
        #pragma unroll
        for (int k = 0; k < BK; k++){
            float4 a4 = *(const float4*)&As[buf][k][ty*4];
            float4 b4 = *(const float4*)&Ws[buf][k][tx*4];
            float a[4] = {a4.x,a4.y,a4.z,a4.w};
            float b[4] = {b4.x,b4.y,b4.z,b4.w};
            #pragma unroll
            for (int r = 0; r < 4; r++)
                #pragma unroll
                for (int c = 0; c < 4; c++)
                    acc[r][c] += a[r]*b[c];
        }
        if (t+1 < nt){
            const int nb = buf ^ 1;
            #pragma unroll
            for (int u = 0; u < 4; u++){
                As[nb][lk][lr+16*u] = ra[u];
                Ws[nb][lk][lr+16*u] = rb[u];
            }
        }
        __syncthreads();
    }
    #pragma unroll
    for (int r = 0; r < 4; r++){
        int gm = m0 + ty*4 + r;
        if (gm >= M) continue;
        #pragma unroll
        for (int c = 0; c < 4; c++){
            int gn = n0 + tx*4 + c;
            if (gn >= N) continue;
            float v = acc[r][c] + bias[gn];
            if (relu) v = fmaxf(v, 0.f);
            Cm[gm*ldc + gn] = v;
        }
    }
}

// ---------------- K1: edge GEMM (blocks 0..127) + gatemap dual GEMM (128..191) ----------------
__global__ __launch_bounds__(NTH)
void k_inner1(const float* __restrict__ hv, const float* __restrict__ nhs,
              const float* __restrict__ dep,
              const float* __restrict__ ae_w1, const float* __restrict__ ae_b1,
              const float* __restrict__ ae_w2,
              const float* __restrict__ gw, const float* __restrict__ mw,
              const float* __restrict__ gb, const float* __restrict__ mb,
              float* __restrict__ part, float* __restrict__ P, float* __restrict__ Pt,
              int i, int j)
{
    __shared__ float sm[3*2*BK*LDS_];
    float* As = sm;
    float* W0 = sm + 2*BK*LDS_;
    float* W1 = sm + 4*BK*LDS_;
    const int tid = threadIdx.x;
    const int lk = tid & 15, lr = tid >> 4;
    const int tx = tid & 15, ty = tid >> 4;

    if (blockIdx.x < NBE){
        // ------------- edge: M=256, N=2004, K=1002 -------------
        const int nt_ = blockIdx.x & (EDGE_NT-1);
        const int mt_ = blockIdx.x >> 5;
        const int m0 = mt_*BM, n0 = nt_*BN;
        float acc[4][4] = {};
        float ra[4], rb[4];
        const int nt = (H2_ + BK - 1)/BK;  // 63

        #pragma unroll
        for (int u = 0; u < 4; u++){
            int gm = m0 + lr + 16*u;
            ra[u] = (lk < H_) ? hv[gm*H_ + lk] : nhs[(gm*S_+j)*H_ + lk - H_];
            int gn = n0 + lr + 16*u;
            rb[u] = (gn < H4_) ? ae_w1[gn*H2_ + lk] : 0.f;
        }
        #pragma unroll
        for (int u = 0; u < 4; u++){
            As[(0*BK+lk)*LDS_ + lr+16*u] = ra[u];
            W0[(0*BK+lk)*LDS_ + lr+16*u] = rb[u];
        }
        __syncthreads();

        for (int t = 0; t < nt; t++){
            const int buf = t & 1;
            if (t+1 < nt){
                int gk = (t+1)*BK + lk;
                #pragma unroll
                for (int u = 0; u < 4; u++){
                    int gm = m0 + lr + 16*u;
                    float v = 0.f;
                    if (gk < H_)       v = hv[gm*H_ + gk];
                    else if (gk < H2_) v = nhs[(gm*S_+j)*H_ + gk - H_];
                    ra[u] = v;
                    int gn = n0 + lr + 16*u;
                    rb[u] = (gn < H4_ && gk < H2_) ? ae_w1[gn*H2_ + gk] : 0.f;
                }
            }
            #pragma unroll
            for (int k = 0; k < BK; k++){
                float4 a4 = *(const float4*)&As[(buf*BK+k)*LDS_ + ty*4];
                float4 b4 = *(const float4*)&W0[(buf*BK+k)*LDS_ + tx*4];
                float a[4] = {a4.x,a4.y,a4.z,a4.w};
                float b[4] = {b4.x,b4.y,b4.z,b4.w};
                #pragma unroll
                for (int r = 0; r < 4; r++)
                    #pragma unroll
                    for (int c = 0; c < 4; c++)
                        acc[r][c] += a[r]*b[c];
            }
            if (t+1 < nt){
                const int nb = buf ^ 1;
                #pragma unroll
                for (int u = 0; u < 4; u++){
                    As[(nb*BK+lk)*LDS_ + lr+16*u] = ra[u];
                    W0[(nb*BK+lk)*LDS_ + lr+16*u] = rb[u];
                }
            }
            __syncthreads();
        }
        // epilogue: relu -> *w2 -> row reduce over this N tile
        #pragma unroll
        for (int r = 0; r < 4; r++){
            float s = 0.f;
            #pragma unroll
            for (int c = 0; c < 4; c++){
                int gn = n0 + tx*4 + c;
                if (gn < H4_)
                    s += fmaxf(acc[r][c] + ae_b1[gn], 0.f) * ae_w2[gn];
            }
            #pragma unroll
            for (int off = 8; off > 0; off >>= 1)
                s += __shfl_down_sync(0xffffffffu, s, off, 16);
            if (tx == 0)
                part[nt_*B_ + m0 + ty*4 + r] = s;
        }
    } else {
        // ------------- gatemap: M=512 (rows: 256 for s=j, 256 for s=i), N=501, K=501 -------------
        const int gbk = blockIdx.x - NBE;
        const int nt_ = gbk & (GM_NT-1);
        const int mt_ = gbk >> 3;
        const int m0 = mt_*BM, n0 = nt_*BN;
        const int s_ = (mt_ < 4) ? j : i;
        float accG[4][4] = {};
        float accM[4][4] = {};
        float ra[4], rg[4], rm[4];
        int   baseu[4];
        float scaleu[4];
        #pragma unroll
        for (int u = 0; u < 4; u++){
            int b = (m0 + lr + 16*u) & (B_-1);
            baseu[u]  = (b*S_ + s_)*H_;
            scaleu[u] = dep[(b*S_ + i)*S_ + s_];
        }
        const int nt = (H_ + BK - 1)/BK;  // 32

        #pragma unroll
        for (int u = 0; u < 4; u++){
            ra[u] = scaleu[u]*nhs[baseu[u] + lk];
            int gn = n0 + lr + 16*u;
            rg[u] = (gn < H_) ? gw[gn*H_ + lk] : 0.f;
            rm[u] = (gn < H_) ? mw[gn*H_ + lk] : 0.f;
        }
        #pragma unroll
        for (int u = 0; u < 4; u++){
            As[(0*BK+lk)*LDS_ + lr+16*u] = ra[u];
            W0[(0*BK+lk)*LDS_ + lr+16*u] = rg[u];
            W1[(0*BK+lk)*LDS_ + lr+16*u] = rm[u];
        }
        __syncthreads();

        for (int t = 0; t < nt; t++){
            const int buf = t & 1;
            if (t+1 < nt){
                int gk = (t+1)*BK + lk;
                #pragma unroll
                for (int u = 0; u < 4; u++){
                    ra[u] = (gk < H_) ? scaleu[u]*nhs[baseu[u] + gk] : 0.f;
                    int gn = n0 + lr + 16*u;
                    bool ok = (gn < H_ && gk < H_);
                    rg[u] = ok ? gw[gn*H_ + gk] : 0.f;
                    rm[u] = ok ? mw[gn*H_ + gk] : 0.f;
                }
            }
            #pragma unroll
            for (int k = 0; k < BK; k++){
                float4 a4 = *(const float4*)&As[(buf*BK+k)*LDS_ + ty*4];
                float4 g4 = *(const float4*)&W0[(buf*BK+k)*LDS_ + tx*4];
                float4 m4 = *(const float4*)&W1[(buf*BK+k)*LDS_ + tx*4];
                float a[4] = {a4.x,a4.y,a4.z,a4.w};
                float g[4] = {g4.x,g4.y,g4.z,g4.w};
                float m[4] = {m4.x,m4.y,m4.z,m4.w};
                #pragma unroll
                for (int r = 0; r < 4; r++)
                    #pragma unroll
                    for (int c = 0; c < 4; c++){
                        accG[r][c] += a[r]*g[c];
                        accM[r][c] += a[r]*m[c];
                    }
            }
            if (t+1 < nt){
                const int nb = buf ^ 1;
                #pragma unroll
                for (int u = 0; u < 4; u++){
                    As[(nb*BK+lk)*LDS_ + lr+16*u] = ra[u];
                    W0[(nb*BK+lk)*LDS_ + lr+16*u] = rg[u];
                    W1[(nb*BK+lk)*LDS_ + lr+16*u] = rm[u];
                }
            }
            __syncthreads();
        }
        #pragma unroll
        for (int r = 0; r < 4; r++){
            int gm = m0 + ty*4 + r;
            int b  = gm & (B_-1);
            float* dst = (mt_ < 4) ? (P + (b*S_ + j)*H_) : (Pt + b*H_);
            #pragma unroll
            for (int c = 0; c < 4; c++){
                int gn = n0 + tx*4 + c;
                if (gn < H_)
                    dst[gn] = sigmoidf_(accG[r][c] + gb[gn]) * (accM[r][c] + mb[gn]);
            }
        }
    }
}

// ---------------- K2: running-sum update + h_in + edge scalar ----------------
__global__ void k_update(float* __restrict__ SUM, float* __restrict__ P,
                         const float* __restrict__ Pt, const float* __restrict__ c0,
                         const float* __restrict__ part, const float* __restrict__ ae_b2,
                         float* __restrict__ out_dep, float* __restrict__ hin,
                         int i, int j, int first)
{
    int idx = blockIdx.x*blockDim.x + threadIdx.x;
    if (idx < B_*H_){
        int b = idx / H_, h = idx - b*H_;
        float pj = P[(b*S_ + j)*H_ + h];
        float pi = Pt[idx];
        float s  = first ? (pj + pi)
                         : (SUM[idx] - P[(b*S_ + i)*H_ + h] + pi + pj);
        SUM[idx] = s;
        P[(b*S_ + i)*H_ + h] = pi;
        int n_act = i - j + 1;
        hin[idx] = s + (float)(S_ - n_act)*c0[h];
    }
    if (idx < B_){
        float e = ae_b2[0];
        #pragma unroll
        for (int t = 0; t < EDGE_NT; t++) e += part[t*B_ + idx];
        out_dep[(idx*S_ + i)*S_ + j] = e;
    }
}

// ---------------- GRU combine ----------------
__global__ void k_gru(const float* __restrict__ gi, int i,
                      const float* gh, const float* gbhh,
                      const float* hid,
                      float* hv, float* nhs, int write_nhs)
{
    int idx = blockIdx.x*blockDim.x + threadIdx.x;
    if (idx >= B_*H_) return;
    int b = idx / H_, h = idx - b*H_;
    const float* gib = gi + (b*S_ + i)*H3_;
    float ir = gib[h], iz = gib[H_ + h], inn = gib[2*H_ + h];
    float hr, hz, hn;
    if (gh){
        const float* g = gh + b*H3_;
        hr = g[h]; hz = g[H_ + h]; hn = g[2*H_ + h];
    } else {
        hr = gbhh[h]; hz = gbhh[H_ + h]; hn = gbhh[2*H_ + h];
    }
    float hd = hid ? hid[idx] : 0.f;
    float r  = sigmoidf_(ir + hr);
    float zz = sigmoidf_(iz + hz);
    float nn = tanhf(inn + r*hn);
    float v  = (1.f - zz)*nn + zz*hd;
    hv[idx] = v;
    if (write_nhs) nhs[(b*S_ + i)*H_ + h] = v;
}

// ---------------- logits layer2 + softmax ----------------
__global__ void av2_softmax(const float* __restrict__ t1, const float* __restrict__ w2,
                            const float* __restrict__ b2, float* __restrict__ out_enc, int i)
{
    int b = blockIdx.x;
    int tid = threadIdx.x;
    float acc[C_] = {};
    const float* row = t1 + b*H2_;
    for (int k = tid; k < H2_; k += 256){
        float a = row[k];
        #pragma unroll
        for (int c = 0; c < C_; c++) acc[c] += a * w2[c*H2_ + k];
    }
    #pragma unroll
    for (int c = 0; c < C_; c++)
        #pragma unroll
        for (int off = 16; off > 0; off >>= 1)
            acc[c] += __shfl_down_sync(0xffffffffu, acc[c], off);
    __shared__ float red[8][C_];
    __shared__ float vals[C_];
    int w = tid >> 5, lane = tid & 31;
    if (lane == 0){
        #pragma unroll
        for (int c = 0; c < C_; c++) red[w][c] = acc[c];
    }
    __syncthreads();
    if (tid < C_){
        float s = b2[tid];
        #pragma unroll
        for (int ww = 0; ww < 8; ww++) s += red[ww][tid];
        vals[tid] = s;
    }
    __syncthreads();
    if (tid == 0){
        float mx = vals[0];
        #pragma unroll
        for (int c = 1; c < C_; c++) mx = fmaxf(mx, vals[c]);
        float e[C_], sum = 0.f;
        #pragma unroll
        for (int c = 0; c < C_; c++){ e[c] = expf(vals[c] - mx); sum += e[c]; }
        float inv = 1.f/sum;
        float* o = out_enc + (b*S_ + i)*C_;
        #pragma unroll
        for (int c = 0; c < C_; c++) o[c] = e[c]*inv;
    }
}

// ---------------- launch ----------------
extern "C" void kernel_launch(void* const* d_in, const int* in_sizes, int n_in,
                              void* d_out, int out_size)
{
    const float* z        = (const float*)d_in[0];
    const float* dep      = (const float*)d_in[1];
    const float* ne       = (const float*)d_in[2];
    const float* lin1_w   = (const float*)d_in[3];
    const float* lin1_b   = (const float*)d_in[4];
    const float* av_w1    = (const float*)d_in[5];
    const float* av_b1    = (const float*)d_in[6];
    const float* av_w2    = (const float*)d_in[7];
    const float* av_b2    = (const float*)d_in[8];
    const float* ae_w1    = (const float*)d_in[9];
    const float* ae_b1    = (const float*)d_in[10];
    const float* ae_w2    = (const float*)d_in[11];
    const float* ae_b2    = (const float*)d_in[12];
    const float* gate_w   = (const float*)d_in[13];
    const float* gate_b   = (const float*)d_in[14];
    const float* map_w    = (const float*)d_in[15];
    const float* map_b    = (const float*)d_in[16];
    const float* gru_w_ih = (const float*)d_in[17];
    const float* gru_w_hh = (const float*)d_in[18];
    const float* gru_b_ih = (const float*)d_in[19];
    const float* gru_b_hh = (const float*)d_in[20];
    (void)in_sizes; (void)n_in; (void)out_size;

    float* out     = (float*)d_out;
    float* out_dep = out;
    float* out_enc = out + B_*S_*S_;

    float *p_hv,*p_nhs,*p_t1,*p_gh,*p_gi,*p_P,*p_Pt,*p_SUM,*p_hin,*p_c0,*p_part;
    cudaGetSymbolAddress((void**)&p_hv,  d_hv);
    cudaGetSymbolAddress((void**)&p_nhs, d_nhs);
    cudaGetSymbolAddress((void**)&p_t1,  d_t1);
    cudaGetSymbolAddress((void**)&p_gh,  d_gh);
    cudaGetSymbolAddress((void**)&p_gi,  d_gi);
    cudaGetSymbolAddress((void**)&p_P,   d_P);
    cudaGetSymbolAddress((void**)&p_Pt,  d_Pt);
    cudaGetSymbolAddress((void**)&p_SUM, d_SUM);
    cudaGetSymbolAddress((void**)&p_hin, d_hin);
    cudaGetSymbolAddress((void**)&p_c0,  d_c0);
    cudaGetSymbolAddress((void**)&p_part,d_part);

    // init
    k_zero<<<(B_*S_*H_ + 255)/256, 256>>>(p_nhs, B_*S_*H_);
    k_zero<<<(B_*S_*S_ + 255)/256, 256>>>(out_dep, B_*S_*S_);
    k_c0<<<(H_ + 255)/256, 256>>>(gate_b, map_b, p_c0);
    // graph_state0
    k_gemm<<<dim3((H_+BN-1)/BN, (B_+BM-1)/BM), NTH>>>(z, L_, lin1_w, lin1_b, p_hv, H_, B_, H_, L_, 0);
    // gi for all (b, step)
    k_gemm<<<dim3((H3_+BN-1)/BN, (B_*S_+BM-1)/BM), NTH>>>(ne, C_, gru_w_ih, gru_b_ih, p_gi, H3_, B_*S_, H3_, C_, 0);

    for (int i = 0; i < S_; i++){
        // logits from graph_state (current hv)
        k_gemm<<<dim3((H2_+BN-1)/BN, (B_+BM-1)/BM), NTH>>>(p_hv, H_, av_w1, av_b1, p_t1, H2_, B_, H2_, H_, 1);
        av2_softmax<<<B_, 256>>>(p_t1, av_w2, av_b2, out_enc, i);

        // hv0 = gru(x_i, h0); do NOT write nhs[i] for i>0 (reference keeps it zero
        // until the first active inner step writes hv_new)
        if (i == 0){
            k_gemm<<<dim3((H3_+BN-1)/BN, (B_+BM-1)/BM), NTH>>>(p_hv, H_, gru_w_hh, gru_b_hh, p_gh, H3_, B_, H3_, H_, 0);
            k_gru<<<(B_*H_+255)/256, 256>>>(p_gi, i, p_gh, nullptr, p_hv, p_hv, p_nhs, 1);
        } else {
            k_gru<<<(B_*H_+255)/256, 256>>>(p_gi, i, nullptr, gru_b_hh, nullptr, p_hv, p_nhs, 0);
        }

        for (int j = i-1; j >= 0; j--){
            int first = (j == i-1);
            k_inner1<<<NBE + NBG, NTH>>>(p_hv, p_nhs, dep, ae_w1, ae_b1, ae_w2,
                                         gate_w, map_w, gate_b, map_b,
                                         p_part, p_P, p_Pt, i, j);
            k_update<<<(B_*H_+255)/256, 256>>>(p_SUM, p_P, p_Pt, p_c0, p_part, ae_b2,
                                               out_dep, p_hin, i, j, first);
            k_gemm<<<dim3((H3_+BN-1)/BN, (B_+BM-1)/BM), NTH>>>(p_hin, H_, gru_w_hh, gru_b_hh, p_gh, H3_, B_, H3_, H_, 0);
            k_gru<<<(B_*H_+255)/256, 256>>>(p_gi, i, p_gh, nullptr, p_hin, p_hv, p_nhs, 1);
        }
    }
}

// round 16
// speedup vs baseline: 1.0076x; 1.0076x over previous
#include <cuda_runtime.h>
#include <math.h>

#define B_ 256
#define S_ 8
#define C_ 8
#define H_ 501
#define L_ 56
#define H2_ 1002
#define H3_ 1503
#define H4_ 2004

#define BM 64
#define BN 64
#define BK 16
#define PAD 4
#define LDS_ (BM + PAD)      // 68 floats, 272B rows -> 16B aligned
#define NTH 256

#define EDGE_NT 32           // ceil(2004/64)
#define EDGE_MT 4            // 256/64
#define NBE (EDGE_NT*EDGE_MT) // 128 edge blocks
#define GM_NT 8              // ceil(501/64)
#define GM_MT 8              // 512/64
#define NBG (GM_NT*GM_MT)    // 64 gatemap blocks

// ---------------- scratch ----------------
__device__ float d_hv  [B_*H_];
__device__ float d_nhs [B_*S_*H_];
__device__ float d_t1  [B_*H2_];
__device__ float d_gh  [B_*H3_];
__device__ float d_gi  [B_*S_*H3_];
__device__ float d_P   [B_*S_*H_];   // P cache per (b,s)
__device__ float d_Pt  [B_*H_];      // new P for row i
__device__ float d_SUM [B_*H_];
__device__ float d_hin [B_*H_];
__device__ float d_c0  [H_];
__device__ float d_part[EDGE_NT*B_];

__device__ __forceinline__ float sigmoidf_(float x){ return 1.f/(1.f+expf(-x)); }

__global__ void k_zero(float* p, int n){
    int i = blockIdx.x*blockDim.x + threadIdx.x;
    if (i < n) p[i] = 0.f;
}
__global__ void k_c0(const float* __restrict__ gb, const float* __restrict__ mb,
                     float* __restrict__ c0){
    int h = blockIdx.x*blockDim.x + threadIdx.x;
    if (h < H_) c0[h] = sigmoidf_(gb[h]) * mb[h];
}

// ---------------- generic double-buffered SGEMM: C = act(A @ W^T + bias) ----------------
__global__ __launch_bounds__(NTH)
void k_gemm(const float* __restrict__ A, int lda,
            const float* __restrict__ W,
            const float* __restrict__ bias,
            float* __restrict__ Cm, int ldc,
            int M, int N, int K, int relu)
{
    __shared__ float As[2][BK][LDS_];
    __shared__ float Ws[2][BK][LDS_];
    const int tid = threadIdx.x;
    const int m0 = blockIdx.y*BM, n0 = blockIdx.x*BN;
    const int lk = tid & 15, lr = tid >> 4;
    const int tx = tid & 15, ty = tid >> 4;
    float acc[4][4] = {};
    float ra[4], rb[4];
    const int nt = (K + BK - 1)/BK;

    #pragma unroll
    for (int u = 0; u < 4; u++){
        int gm = m0 + lr + 16*u;
        int gn = n0 + lr + 16*u;
        ra[u] = (lk < K && gm < M) ? A[gm*lda + lk] : 0.f;
        rb[u] = (lk < K && gn < N) ? W[gn*K  + lk] : 0.f;
    }
    #pragma unroll
    for (int u = 0; u < 4; u++){
        As[0][lk][lr+16*u] = ra[u];
        Ws[0][lk][lr+16*u] = rb[u];
    }
    __syncthreads();

    for (int t = 0; t < nt; t++){
        const int buf = t & 1;
        if (t+1 < nt){
            int gk = (t+1)*BK + lk;
            #pragma unroll
            for (int u = 0; u < 4; u++){
                int gm = m0 + lr + 16*u;
                int gn = n0 + lr + 16*u;
                ra[u] = (gk < K && gm < M) ? A[gm*lda + gk] : 0.f;
                rb[u] = (gk < K && gn < N) ? W[gn*K  + gk] : 0.f;
            }
        }
        #pragma unroll
        for (int k = 0; k < BK; k++){
            float4 a4 = *(const float4*)&As[buf][k][ty*4];
            float4 b4 = *(const float4*)&Ws[buf][k][tx*4];
            float a[4] = {a4.x,a4.y,a4.z,a4.w};
            float b[4] = {b4.x,b4.y,b4.z,b4.w};
            #pragma unroll
            for (int r = 0; r < 4; r++)
                #pragma unroll
                for (int c = 0; c < 4; c++)
                    acc[r][c] += a[r]*b[c];
        }
        if (t+1 < nt){
            const int nb = buf ^ 1;
            #pragma unroll
            for (int u = 0; u < 4; u++){
                As[nb][lk][lr+16*u] = ra[u];
                Ws[nb][lk][lr+16*u] = rb[u];
            }
        }
        __syncthreads();
    }
    #pragma unroll
    for (int r = 0; r < 4; r++){
        int gm = m0 + ty*4 + r;
        if (gm >= M) continue;
        #pragma unroll
        for (int c = 0; c < 4; c++){
            int gn = n0 + tx*4 + c;
            if (gn >= N) continue;
            float v = acc[r][c] + bias[gn];
            if (relu) v = fmaxf(v, 0.f);
            Cm[gm*ldc + gn] = v;
        }
    }
}

// ---------------- K1: edge GEMM (blocks 0..127) + gatemap dual GEMM (128..191) ----------------
__global__ __launch_bounds__(NTH)
void k_inner1(const float* __restrict__ hv, const float* __restrict__ nhs,
              const float* __restrict__ dep,
              const float* __restrict__ ae_w1, const float* __restrict__ ae_b1,
              const float* __restrict__ ae_w2,
              const float* __restrict__ gw, const float* __restrict__ mw,
              const float* __restrict__ gb, const float* __restrict__ mb,
              float* __restrict__ part, float* __restrict__ P, float* __restrict__ Pt,
              int i, int j)
{
    __shared__ float sm[3*2*BK*LDS_];
    float* As = sm;
    float* W0 = sm + 2*BK*LDS_;
    float* W1 = sm + 4*BK*LDS_;
    const int tid = threadIdx.x;
    const int lk = tid & 15, lr = tid >> 4;
    const int tx = tid & 15, ty = tid >> 4;

    if (blockIdx.x < NBE){
        // ------------- edge: M=256, N=2004, K=1002 -------------
        const int nt_ = blockIdx.x & (EDGE_NT-1);
        const int mt_ = blockIdx.x >> 5;
        const int m0 = mt_*BM, n0 = nt_*BN;
        float acc[4][4] = {};
        float ra[4], rb[4];
        const int nt = (H2_ + BK - 1)/BK;  // 63

        #pragma unroll
        for (int u = 0; u < 4; u++){
            int gm = m0 + lr + 16*u;
            ra[u] = (lk < H_) ? hv[gm*H_ + lk] : nhs[(gm*S_+j)*H_ + lk - H_];
            int gn = n0 + lr + 16*u;
            rb[u] = (gn < H4_) ? ae_w1[gn*H2_ + lk] : 0.f;
        }
        #pragma unroll
        for (int u = 0; u < 4; u++){
            As[(0*BK+lk)*LDS_ + lr+16*u] = ra[u];
            W0[(0*BK+lk)*LDS_ + lr+16*u] = rb[u];
        }
        __syncthreads();

        for (int t = 0; t < nt; t++){
            const int buf = t & 1;
            if (t+1 < nt){
                int gk = (t+1)*BK + lk;
                #pragma unroll
                for (int u = 0; u < 4; u++){
                    int gm = m0 + lr + 16*u;
                    float v = 0.f;
                    if (gk < H_)       v = hv[gm*H_ + gk];
                    else if (gk < H2_) v = nhs[(gm*S_+j)*H_ + gk - H_];
                    ra[u] = v;
                    int gn = n0 + lr + 16*u;
                    rb[u] = (gn < H4_ && gk < H2_) ? ae_w1[gn*H2_ + gk] : 0.f;
                }
            }
            #pragma unroll
            for (int k = 0; k < BK; k++){
                float4 a4 = *(const float4*)&As[(buf*BK+k)*LDS_ + ty*4];
                float4 b4 = *(const float4*)&W0[(buf*BK+k)*LDS_ + tx*4];
                float a[4] = {a4.x,a4.y,a4.z,a4.w};
                float b[4] = {b4.x,b4.y,b4.z,b4.w};
                #pragma unroll
                for (int r = 0; r < 4; r++)
                    #pragma unroll
                    for (int c = 0; c < 4; c++)
                        acc[r][c] += a[r]*b[c];
            }
            if (t+1 < nt){
                const int nb = buf ^ 1;
                #pragma unroll
                for (int u = 0; u < 4; u++){
                    As[(nb*BK+lk)*LDS_ + lr+16*u] = ra[u];
                    W0[(nb*BK+lk)*LDS_ + lr+16*u] = rb[u];
                }
            }
            __syncthreads();
        }
        // epilogue: relu -> *w2 -> row reduce over this N tile
        #pragma unroll
        for (int r = 0; r < 4; r++){
            float s = 0.f;
            #pragma unroll
            for (int c = 0; c < 4; c++){
                int gn = n0 + tx*4 + c;
                if (gn < H4_)
                    s += fmaxf(acc[r][c] + ae_b1[gn], 0.f) * ae_w2[gn];
            }
            #pragma unroll
            for (int off = 8; off > 0; off >>= 1)
                s += __shfl_down_sync(0xffffffffu, s, off, 16);
            if (tx == 0)
                part[nt_*B_ + m0 + ty*4 + r] = s;
        }
    } else {
        // ------------- gatemap: M=512 (rows: 256 for s=j, 256 for s=i), N=501, K=501 -------------
        const int gbk = blockIdx.x - NBE;
        const int nt_ = gbk & (GM_NT-1);
        const int mt_ = gbk >> 3;
        const int m0 = mt_*BM, n0 = nt_*BN;
        const int s_ = (mt_ < 4) ? j : i;
        float accG[4][4] = {};
        float accM[4][4] = {};
        float ra[4], rg[4], rm[4];
        int   baseu[4];
        float scaleu[4];
        #pragma unroll
        for (int u = 0; u < 4; u++){
            int b = (m0 + lr + 16*u) & (B_-1);
            baseu[u]  = (b*S_ + s_)*H_;
            scaleu[u] = dep[(b*S_ + i)*S_ + s_];
        }
        const int nt = (H_ + BK - 1)/BK;  // 32

        #pragma unroll
        for (int u = 0; u < 4; u++){
            ra[u] = scaleu[u]*nhs[baseu[u] + lk];
            int gn = n0 + lr + 16*u;
            rg[u] = (gn < H_) ? gw[gn*H_ + lk] : 0.f;
            rm[u] = (gn < H_) ? mw[gn*H_ + lk] : 0.f;
        }
        #pragma unroll
        for (int u = 0; u < 4; u++){
            As[(0*BK+lk)*LDS_ + lr+16*u] = ra[u];
            W0[(0*BK+lk)*LDS_ + lr+16*u] = rg[u];
            W1[(0*BK+lk)*LDS_ + lr+16*u] = rm[u];
        }
        __syncthreads();

        for (int t = 0; t < nt; t++){
            const int buf = t & 1;
            if (t+1 < nt){
                int gk = (t+1)*BK + lk;
                #pragma unroll
                for (int u = 0; u < 4; u++){
                    ra[u] = (gk < H_) ? scaleu[u]*nhs[baseu[u] + gk] : 0.f;
                    int gn = n0 + lr + 16*u;
                    bool ok = (gn < H_ && gk < H_);
                    rg[u] = ok ? gw[gn*H_ + gk] : 0.f;
                    rm[u] = ok ? mw[gn*H_ + gk] : 0.f;
                }
            }
            #pragma unroll
            for (int k = 0; k < BK; k++){
                float4 a4 = *(const float4*)&As[(buf*BK+k)*LDS_ + ty*4];
                float4 g4 = *(const float4*)&W0[(buf*BK+k)*LDS_ + tx*4];
                float4 m4 = *(const float4*)&W1[(buf*BK+k)*LDS_ + tx*4];
                float a[4] = {a4.x,a4.y,a4.z,a4.w};
                float g[4] = {g4.x,g4.y,g4.z,g4.w};
                float m[4] = {m4.x,m4.y,m4.z,m4.w};
                #pragma unroll
                for (int r = 0; r < 4; r++)
                    #pragma unroll
                    for (int c = 0; c < 4; c++){
                        accG[r][c] += a[r]*g[c];
                        accM[r][c] += a[r]*m[c];
                    }
            }
            if (t+1 < nt){
                const int nb = buf ^ 1;
                #pragma unroll
                for (int u = 0; u < 4; u++){
                    As[(nb*BK+lk)*LDS_ + lr+16*u] = ra[u];
                    W0[(nb*BK+lk)*LDS_ + lr+16*u] = rg[u];
                    W1[(nb*BK+lk)*LDS_ + lr+16*u] = rm[u];
                }
            }
            __syncthreads();
        }
        #pragma unroll
        for (int r = 0; r < 4; r++){
            int gm = m0 + ty*4 + r;
            int b  = gm & (B_-1);
            float* dst = (mt_ < 4) ? (P + (b*S_ + j)*H_) : (Pt + b*H_);
            #pragma unroll
            for (int c = 0; c < 4; c++){
                int gn = n0 + tx*4 + c;
                if (gn < H_)
                    dst[gn] = sigmoidf_(accG[r][c] + gb[gn]) * (accM[r][c] + mb[gn]);
            }
        }
    }
}

// ---------------- K2: running-sum update + h_in + edge scalar ----------------
__global__ void k_update(float* __restrict__ SUM, float* __restrict__ P,
                         const float* __restrict__ Pt, const float* __restrict__ c0,
                         const float* __restrict__ part, const float* __restrict__ ae_b2,
                         float* __restrict__ out_dep, float* __restrict__ hin,
                         int i, int j, int first)
{
    int idx = blockIdx.x*blockDim.x + threadIdx.x;
    if (idx < B_*H_){
        int b = idx / H_, h = idx - b*H_;
        float pj = P[(b*S_ + j)*H_ + h];
        float pi = Pt[idx];
        float s  = first ? (pj + pi)
                         : (SUM[idx] - P[(b*S_ + i)*H_ + h] + pi + pj);
        SUM[idx] = s;
        P[(b*S_ + i)*H_ + h] = pi;
        int n_act = i - j + 1;
        hin[idx] = s + (float)(S_ - n_act)*c0[h];
    }
    if (idx < B_){
        float e = ae_b2[0];
        #pragma unroll
        for (int t = 0; t < EDGE_NT; t++) e += part[t*B_ + idx];
        out_dep[(idx*S_ + i)*S_ + j] = e;
    }
}

// ---------------- GRU combine ----------------
__global__ void k_gru(const float* __restrict__ gi, int i,
                      const float* gh, const float* gbhh,
                      const float* hid,
                      float* hv, float* nhs, int write_nhs)
{
    int idx = blockIdx.x*blockDim.x + threadIdx.x;
    if (idx >= B_*H_) return;
    int b = idx / H_, h = idx - b*H_;
    const float* gib = gi + (b*S_ + i)*H3_;
    float ir = gib[h], iz = gib[H_ + h], inn = gib[2*H_ + h];
    float hr, hz, hn;
    if (gh){
        const float* g = gh + b*H3_;
        hr = g[h]; hz = g[H_ + h]; hn = g[2*H_ + h];
    } else {
        hr = gbhh[h]; hz = gbhh[H_ + h]; hn = gbhh[2*H_ + h];
    }
    float hd = hid ? hid[idx] : 0.f;
    float r  = sigmoidf_(ir + hr);
    float zz = sigmoidf_(iz + hz);
    float nn = tanhf(inn + r*hn);
    float v  = (1.f - zz)*nn + zz*hd;
    hv[idx] = v;
    if (write_nhs) nhs[(b*S_ + i)*H_ + h] = v;
}

// ---------------- logits layer2 + softmax ----------------
__global__ void av2_softmax(const float* __restrict__ t1, const float* __restrict__ w2,
                            const float* __restrict__ b2, float* __restrict__ out_enc, int i)
{
    int b = blockIdx.x;
    int tid = threadIdx.x;
    float acc[C_] = {};
    const float* row = t1 + b*H2_;
    for (int k = tid; k < H2_; k += 256){
        float a = row[k];
        #pragma unroll
        for (int c = 0; c < C_; c++) acc[c] += a * w2[c*H2_ + k];
    }
    #pragma unroll
    for (int c = 0; c < C_; c++)
        #pragma unroll
        for (int off = 16; off > 0; off >>= 1)
            acc[c] += __shfl_down_sync(0xffffffffu, acc[c], off);
    __shared__ float red[8][C_];
    __shared__ float vals[C_];
    int w = tid >> 5, lane = tid & 31;
    if (lane == 0){
        #pragma unroll
        for (int c = 0; c < C_; c++) red[w][c] = acc[c];
    }
    __syncthreads();
    if (tid < C_){
        float s = b2[tid];
        #pragma unroll
        for (int ww = 0; ww < 8; ww++) s += red[ww][tid];
        vals[tid] = s;
    }
    __syncthreads();
    if (tid == 0){
        float mx = vals[0];
        #pragma unroll
        for (int c = 1; c < C_; c++) mx = fmaxf(mx, vals[c]);
        float e[C_], sum = 0.f;
        #pragma unroll
        for (int c = 0; c < C_; c++){ e[c] = expf(vals[c] - mx); sum += e[c]; }
        float inv = 1.f/sum;
        float* o = out_enc + (b*S_ + i)*C_;
        #pragma unroll
        for (int c = 0; c < C_; c++) o[c] = e[c]*inv;
    }
}

// ---------------- launch ----------------
extern "C" void kernel_launch(void* const* d_in, const int* in_sizes, int n_in,
                              void* d_out, int out_size)
{
    const float* z        = (const float*)d_in[0];
    const float* dep      = (const float*)d_in[1];
    const float* ne       = (const float*)d_in[2];
    const float* lin1_w   = (const float*)d_in[3];
    const float* lin1_b   = (const float*)d_in[4];
    const float* av_w1    = (const float*)d_in[5];
    const float* av_b1    = (const float*)d_in[6];
    const float* av_w2    = (const float*)d_in[7];
    const float* av_b2    = (const float*)d_in[8];
    const float* ae_w1    = (const float*)d_in[9];
    const float* ae_b1    = (const float*)d_in[10];
    const float* ae_w2    = (const float*)d_in[11];
    const float* ae_b2    = (const float*)d_in[12];
    const float* gate_w   = (const float*)d_in[13];
    const float* gate_b   = (const float*)d_in[14];
    const float* map_w    = (const float*)d_in[15];
    const float* map_b    = (const float*)d_in[16];
    const float* gru_w_ih = (const float*)d_in[17];
    const float* gru_w_hh = (const float*)d_in[18];
    const float* gru_b_ih = (const float*)d_in[19];
    const float* gru_b_hh = (const float*)d_in[20];
    (void)in_sizes; (void)n_in; (void)out_size;

    float* out     = (float*)d_out;
    float* out_dep = out;
    float* out_enc = out + B_*S_*S_;

    float *p_hv,*p_nhs,*p_t1,*p_gh,*p_gi,*p_P,*p_Pt,*p_SUM,*p_hin,*p_c0,*p_part;
    cudaGetSymbolAddress((void**)&p_hv,  d_hv);
    cudaGetSymbolAddress((void**)&p_nhs, d_nhs);
    cudaGetSymbolAddress((void**)&p_t1,  d_t1);
    cudaGetSymbolAddress((void**)&p_gh,  d_gh);
    cudaGetSymbolAddress((void**)&p_gi,  d_gi);
    cudaGetSymbolAddress((void**)&p_P,   d_P);
    cudaGetSymbolAddress((void**)&p_Pt,  d_Pt);
    cudaGetSymbolAddress((void**)&p_SUM, d_SUM);
    cudaGetSymbolAddress((void**)&p_hin, d_hin);
    cudaGetSymbolAddress((void**)&p_c0,  d_c0);
    cudaGetSymbolAddress((void**)&p_part,d_part);

    // init
    k_zero<<<(B_*S_*H_ + 255)/256, 256>>>(p_nhs, B_*S_*H_);
    k_zero<<<(B_*S_*S_ + 255)/256, 256>>>(out_dep, B_*S_*S_);
    k_c0<<<(H_ + 255)/256, 256>>>(gate_b, map_b, p_c0);
    // graph_state0
    k_gemm<<<dim3((H_+BN-1)/BN, (B_+BM-1)/BM), NTH>>>(z, L_, lin1_w, lin1_b, p_hv, H_, B_, H_, L_, 0);
    // gi for all (b, step)
    k_gemm<<<dim3((H3_+BN-1)/BN, (B_*S_+BM-1)/BM), NTH>>>(ne, C_, gru_w_ih, gru_b_ih, p_gi, H3_, B_*S_, H3_, C_, 0);

    for (int i = 0; i < S_; i++){
        // logits from graph_state (current hv)
        k_gemm<<<dim3((H2_+BN-1)/BN, (B_+BM-1)/BM), NTH>>>(p_hv, H_, av_w1, av_b1, p_t1, H2_, B_, H2_, H_, 1);
        av2_softmax<<<B_, 256>>>(p_t1, av_w2, av_b2, out_enc, i);

        // hv0 = gru(x_i, h0); do NOT write nhs[i] for i>0 (reference keeps it zero
        // until the first active inner step writes hv_new)
        if (i == 0){
            k_gemm<<<dim3((H3_+BN-1)/BN, (B_+BM-1)/BM), NTH>>>(p_hv, H_, gru_w_hh, gru_b_hh, p_gh, H3_, B_, H3_, H_, 0);
            k_gru<<<(B_*H_+255)/256, 256>>>(p_gi, i, p_gh, nullptr, p_hv, p_hv, p_nhs, 1);
        } else {
            k_gru<<<(B_*H_+255)/256, 256>>>(p_gi, i, nullptr, gru_b_hh, nullptr, p_hv, p_nhs, 0);
        }

        for (int j = i-1; j >= 0; j--){
            int first = (j == i-1);
            k_inner1<<<NBE + NBG, NTH>>>(p_hv, p_nhs, dep, ae_w1, ae_b1, ae_w2,
                                         gate_w, map_w, gate_b, map_b,
                                         p_part, p_P, p_Pt, i, j);
            k_update<<<(B_*H_+255)/256, 256>>>(p_SUM, p_P, p_Pt, p_c0, p_part, ae_b2,
                                               out_dep, p_hin, i, j, first);
            k_gemm<<<dim3((H3_+BN-1)/BN, (B_+BM-1)/BM), NTH>>>(p_hin, H_, gru_w_hh, gru_b_hh, p_gh, H3_, B_, H3_, H_, 0);
            k_gru<<<(B_*H_+255)/256, 256>>>(p_gi, i, p_gh, nullptr, p_hin, p_hv, p_nhs, 1);
        }
    }
}